// round 2
// baseline (speedup 1.0000x reference)
#include <cuda_runtime.h>
#include <math.h>

#define STEPF   0.1f
#define MAXL    1024
#define MAXNS   64
#define DELAY_N 30
#define TPB     64

// packed dual-FMA: d.lo = a.lo*b.lo + c.lo ; d.hi = a.hi*b.hi + c.hi
__device__ __forceinline__ unsigned long long fma2(unsigned long long a,
                                                   unsigned long long b,
                                                   unsigned long long c) {
    unsigned long long d;
    asm("fma.rn.f32x2 %0, %1, %2, %3;" : "=l"(d) : "l"(a), "l"(b), "l"(c));
    return d;
}

__device__ __forceinline__ unsigned long long pack2(float lo, float hi) {
    unsigned long long d;
    asm("mov.b64 %0, {%1, %2};" : "=l"(d) : "f"(lo), "f"(hi));
    return d;
}

__device__ __forceinline__ void unpack2(unsigned long long v, float& lo, float& hi) {
    asm("mov.b64 {%0, %1}, %2;" : "=f"(lo), "=f"(hi) : "l"(v));
}

// ---------------------------------------------------------------------------
// Fused kernel: per-block prep (AIF interp + delay, searchsorted indices) in
// shared, then per-pixel bi-exponential recurrence convolution + SPGR signal.
// ---------------------------------------------------------------------------
__global__ void __launch_bounds__(TPB)
dce_main_kernel(const float* __restrict__ param,
                const float* __restrict__ sample_time,
                const float* __restrict__ Cp,
                float* __restrict__ out, int npix, int ns)
{
    __shared__ float2 s_aif2[MAXL];     // AIF duplicated into both lanes
    __shared__ int    s_idx[MAXNS];
    __shared__ float  s_st[MAXNS];
    __shared__ float  s_cp[MAXNS];

    const int tid = threadIdx.x;

    // stage the 50-point inputs
    for (int j = tid; j < ns; j += TPB) { s_st[j] = sample_time[j]; s_cp[j] = Cp[j]; }
    __syncthreads();

    // L = round(t_end / STEP) + 1 (reference computes in float64)
    const double t_end = (double)s_st[ns - 1];
    int L = (int)llrint(t_end / 0.1) + 1;
    if (L > MAXL) L = MAXL;

    // aif[i] = 0 for i < DELAY, else interp(t=(i-DELAY)*0.1f, sample_time, Cp)
    for (int i = tid; i < L; i += TPB) {
        float val = 0.f;
        if (i >= DELAY_N) {
            const float t = (float)(i - DELAY_N) * STEPF;
            if (t <= s_st[0]) {
                val = s_cp[0];
            } else if (t >= s_st[ns - 1]) {
                val = s_cp[ns - 1];
            } else {
                int lo = 0, hi = ns - 1;
                while (lo + 1 < hi) {
                    int mid = (lo + hi) >> 1;
                    if (s_st[mid] <= t) lo = mid; else hi = mid;
                }
                const float x0 = s_st[lo], x1 = s_st[lo + 1];
                val = s_cp[lo] + (t - x0) * (s_cp[lo + 1] - s_cp[lo]) / (x1 - x0);
            }
        }
        s_aif2[i] = make_float2(val, val);
    }

    // idx[j] = searchsorted(t_samp, sample_time[j], 'left'), clamped like JAX
    for (int j = tid; j < ns; j += TPB) {
        const float st = s_st[j];
        int lo = 0, hi = L;
        while (lo < hi) {
            int mid = (lo + hi) >> 1;
            if ((float)mid * STEPF < st) lo = mid + 1; else hi = mid;  // same IEEE ops as jnp
        }
        s_idx[j] = lo < (L - 1) ? lo : (L - 1);
    }
    __syncthreads();

    const int pix = blockIdx.x * TPB + tid;
    if (pix >= npix) return;

    const float ve  = param[pix];
    const float vp  = param[npix + pix];
    const float fpp = param[2 * npix + pix];
    const float ps  = param[3 * npix + pix];

    const float Te = ve / ps;
    const float T  = (vp + ve) / fpp;
    const float Tc = vp / fpp;
    const float s  = T + Te;
    const float disc = sqrtf(fmaxf(s * s - 4.f * Tc * Te, 0.f));
    const float inv2 = 1.f / (2.f * Tc * Te);
    const float thp = (s + disc) * inv2;
    const float thm = (s - disc) * inv2;

    const float rm = expf(-thm * STEPF);   // compounds over ~589 steps: keep precise
    const float rp = expf(-thp * STEPF);

    // geometric-series normalization sums via expm1f
    const float Lf  = (float)L;
    const float SEm = (-expm1f(-thm * STEPF * Lf)) / (-expm1f(-thm * STEPF));
    const float SEp = (-expm1f(-thp * STEPF * Lf)) / (-expm1f(-thp * STEPF));

    const float cm  = 1.f - Te * thm;
    const float cpp = Te * thp - 1.f;
    const float inv_she = 1.f / (SEm - SEp);
    const float inv_shp = 1.f / fmaf(cm, SEm, cpp * SEp);

    // SPGR constants
    const float cosfa = 0.98480775301220806f;    // cos(10 deg)
    const float E1    = expf(-0.00487f);
    const float M0t   = 100.f * (1.f - cosfa * E1) / (1.f - E1);
    const float base  = 100.f - M0t * (1.f - E1) / (1.f - E1 * cosfa);

    const unsigned long long* __restrict__ aifu =
        reinterpret_cast<const unsigned long long*>(s_aif2);

    const unsigned long long R = pack2(rm, rp);
    unsigned long long S = 0ull;                 // (Sm, Sp) = (0, 0)

    int m = 0;
    for (int j = 0; j < ns; ++j) {
        const int target = s_idx[j];
        const int n = target - m + 1;
        #pragma unroll 4
        for (int k = 0; k < n; ++k) {
            S = fma2(S, R, aifu[m + k]);         // S = S*r + aif  (both streams)
        }
        m = target + 1;

        float Sm, Sp;
        unpack2(S, Sm, Sp);
        const float ce   = inv_she * (Sm - Sp);
        const float cpv  = inv_shp * fmaf(cm, Sm, cpp * Sp);
        const float conc = vp * cpv + ve * ce;
        const float E1CA = __expf(-0.00487f * fmaf(4.3f, conc, 1.0f));
        const float sig  = __fdividef(M0t * (1.f - E1CA), 1.f - E1CA * cosfa) + base;
        out[(size_t)j * npix + pix] = sig;
    }
}

extern "C" void kernel_launch(void* const* d_in, const int* in_sizes, int n_in,
                              void* d_out, int out_size)
{
    const float* param       = (const float*)d_in[0];
    const float* sample_time = (const float*)d_in[1];
    const float* Cp          = (const float*)d_in[2];
    float* out = (float*)d_out;

    const int ns   = in_sizes[1];
    const int npix = in_sizes[0] / 4;

    const int blocks = (npix + TPB - 1) / TPB;
    dce_main_kernel<<<blocks, TPB>>>(param, sample_time, Cp, out, npix, ns);
}